// round 12
// baseline (speedup 1.0000x reference)
#include <cuda_runtime.h>
#include <cuda_fp16.h>
#include <cstdint>
#include <math.h>

#define NN 8192
#define IN_F 128
#define OUT_F 64
#define ALPHA 0.2f
#define LOG2E 1.4426950408889634f
#define NCH 64             // 32-col chunks over a 2048-col quarter
#define SBCH 8             // chunks per B superblock (256 cols)
#define SBN (NCH / SBCH)   // 8 superblocks
#define BPITCH 528         // B smem row pitch -> 16B rotation, conflict-free
#define BBYTES (64 * BPITCH)
#define SPITCH 80          // score tile pitch -> 16B rotation, conflict-free
#define SWARP (2 * 16 * SPITCH)      // per-warp double-buffered score tile
#define SMEMT (2 * BBYTES + 8 * SWARP)   // 88064 B -> 2 CTAs/SM

// ---------------- device scratch (allocation-free rule) ----------------
__device__ float  g_s1[NN];
__device__ float  g_s2[NN];
__device__ float  g_M;
__device__ __half g_hT[(size_t)OUT_F * NN];     // H^T fp16, [f][j]
__device__ float  g_num[(size_t)4 * NN * OUT_F];
__device__ float  g_den[4 * NN];

// ---------------------------------------------------------------------------
// Kernel A: h = feat @ W^T ; s1/s2 row scores ; g_hT = fp16(h)^T
// ---------------------------------------------------------------------------
__global__ __launch_bounds__(1024) void k_proj(const float* __restrict__ feat,
                                               const float* __restrict__ W,
                                               const float* __restrict__ a) {
    __shared__ float Ws[OUT_F][IN_F + 4];
    __shared__ float Fs[16][IN_F];
    __shared__ float red1[32], red2[32];
    __shared__ __half Ts[OUT_F][18];

    int tid = threadIdx.x;
    int i0  = blockIdx.x * 16;

    for (int t = tid; t < OUT_F * IN_F; t += 1024)
        Ws[t / IN_F][t % IN_F] = W[t];
    for (int t = tid; t < 16 * IN_F; t += 1024)
        Fs[t / IN_F][t % IN_F] = feat[(size_t)(i0 + t / IN_F) * IN_F + (t % IN_F)];
    __syncthreads();

    int f = tid & 63;
    int r = tid >> 6;
    float acc = 0.f;
#pragma unroll
    for (int k = 0; k < IN_F; k += 4) {
        float4 fv = *(const float4*)&Fs[r][k];
        float4 wv = *(const float4*)&Ws[f][k];
        acc += fv.x * wv.x + fv.y * wv.y + fv.z * wv.z + fv.w * wv.w;
    }

    Ts[f][r] = __float2half(acc);

    float t1 = acc * a[f];
    float t2 = acc * a[OUT_F + f];
#pragma unroll
    for (int off = 16; off; off >>= 1) {
        t1 += __shfl_xor_sync(0xffffffffu, t1, off);
        t2 += __shfl_xor_sync(0xffffffffu, t2, off);
    }
    int w = tid >> 5;
    if ((tid & 31) == 0) { red1[w] = t1; red2[w] = t2; }
    __syncthreads();
    if (tid < 16) {
        g_s1[i0 + tid] = red1[2 * tid] + red1[2 * tid + 1];
        g_s2[i0 + tid] = red2[2 * tid] + red2[2 * tid + 1];
    }
    if (tid < 512) {
        int ff = tid >> 3, u = tid & 7;
        __half2 pk = __halves2half2(Ts[ff][2 * u], Ts[ff][2 * u + 1]);
        *(__half2*)&g_hT[(size_t)ff * NN + i0 + 2 * u] = pk;
    }
}

// ---------------------------------------------------------------------------
// Kernel B: g_M = max_j s2[j]
// ---------------------------------------------------------------------------
__global__ __launch_bounds__(256) void k_max() {
    __shared__ float red[8];
    int tid = threadIdx.x;
    float m = -1e30f;
    for (int i = tid; i < NN; i += 256) m = fmaxf(m, g_s2[i]);
#pragma unroll
    for (int off = 16; off; off >>= 1)
        m = fmaxf(m, __shfl_xor_sync(0xffffffffu, m, off));
    if ((tid & 31) == 0) red[tid >> 5] = m;
    __syncthreads();
    if (tid == 0) {
        float mm = red[0];
#pragma unroll
        for (int i = 1; i < 8; i++) mm = fmaxf(mm, red[i]);
        g_M = mm;
    }
}

// ---------------------------------------------------------------------------
// Main kernel. 256 CTAs (64 row-tiles x 4 quarters) x 256 threads, 2 CTAs/SM.
// Two-stage per-warp software pipeline: scores(c) then MMA(c-1) -> the
// STS->LDSM->HMMA chain of chunk c-1 overlaps the MUFU-heavy scores of c.
// Pipeline drains at each superblock boundary, preserving barrier structure.
// ---------------------------------------------------------------------------
struct ChunkBuf {
    float4 G[4];
    float4 S[4];
    float4 Z;
};

__device__ __forceinline__ void load_chunk(const float* __restrict__ gp0,
                                           const float* __restrict__ sp0,
                                           const float* __restrict__ s2p,
                                           int c, ChunkBuf& b) {
    size_t off = (size_t)c * 32;
#pragma unroll
    for (int i = 0; i < 4; i++) {
        b.G[i] = __ldcs((const float4*)(gp0 + off + (size_t)(4 * i) * NN));
        b.S[i] = __ldcs((const float4*)(sp0 + off + (size_t)(4 * i) * NN));
    }
    b.Z = *(const float4*)(s2p + off);
}

__device__ __forceinline__ void mma16816(float* d, const uint32_t* a,
                                         uint32_t b0, uint32_t b1) {
    asm volatile(
        "mma.sync.aligned.m16n8k16.row.col.f32.f16.f16.f32 "
        "{%0,%1,%2,%3},{%4,%5,%6,%7},{%8,%9},{%0,%1,%2,%3};"
        : "+f"(d[0]), "+f"(d[1]), "+f"(d[2]), "+f"(d[3])
        : "r"(a[0]), "r"(a[1]), "r"(a[2]), "r"(a[3]), "r"(b0), "r"(b1));
}

// Stage 1: scores for chunk from `cur` -> smem score buffer `par`
__device__ __forceinline__ void do_scores(ChunkBuf& cur, int par, uint32_t sts0,
                                          const float (&s1v)[4], const float (&bnv)[4],
                                          float (&dloc)[4]) {
    uint32_t bufo = (uint32_t)par * (16 * SPITCH);
#pragma unroll
    for (int i = 0; i < 4; i++) {
        float4 g = cur.G[i], s = cur.S[i];
        float clx = (g.x + s.x) * LOG2E;
        float cly = (g.y + s.y) * LOG2E;
        float clz = (g.z + s.z) * LOG2E;
        float clw = (g.w + s.w) * LOG2E;
        float s1 = s1v[i], bn = bnv[i];
        float x0 = s1 + cur.Z.x, x1 = s1 + cur.Z.y;
        float x2 = s1 + cur.Z.z, x3 = s1 + cur.Z.w;
        float l0 = fmaxf(x0, ALPHA * x0), l1 = fmaxf(x1, ALPHA * x1);
        float l2 = fmaxf(x2, ALPHA * x2), l3 = fmaxf(x3, ALPHA * x3);
        float p0 = (clx > 0.f) ? exp2f(fmaf(l0, clx, -bn)) : 0.f;
        float p1 = (cly > 0.f) ? exp2f(fmaf(l1, cly, -bn)) : 0.f;
        float p2 = (clz > 0.f) ? exp2f(fmaf(l2, clz, -bn)) : 0.f;
        float p3 = (clw > 0.f) ? exp2f(fmaf(l3, clw, -bn)) : 0.f;
        __half2 lo = __floats2half2_rn(p0, p1);
        __half2 hi = __floats2half2_rn(p2, p3);
        __half2 dsum = __hadd2(lo, hi);
        float2 d = __half22float2(dsum);
        dloc[i] += d.x + d.y;
        asm volatile("st.shared.v2.b32 [%0], {%1,%2};"
                     :: "r"(sts0 + bufo + (uint32_t)(4 * i) * SPITCH),
                        "r"(*(uint32_t*)&lo), "r"(*(uint32_t*)&hi));
    }
}

// Stage 2: MMA for chunk c (scores in buffer `par`, published by prior syncwarp)
__device__ __forceinline__ void do_mma(int c, int par, uint32_t lda0, uint32_t ldb,
                                       float (&acc)[8][4]) {
    uint32_t af[2][4];
    uint32_t la = lda0 + (uint32_t)par * (16 * SPITCH);
#pragma unroll
    for (int kk = 0; kk < 2; kk++)
        asm volatile(
            "ldmatrix.sync.aligned.m8n8.x4.shared.b16 {%0,%1,%2,%3}, [%4];"
            : "=r"(af[kk][0]), "=r"(af[kk][1]), "=r"(af[kk][2]), "=r"(af[kk][3])
            : "r"(la + kk * 32));

    uint32_t bb = ldb + (uint32_t)(c & (SBCH - 1)) * 64;
#pragma unroll
    for (int kk = 0; kk < 2; kk++) {
#pragma unroll
        for (int t = 0; t < 4; t++) {
            uint32_t b0, b1, b2, b3;
            asm volatile(
                "ldmatrix.sync.aligned.m8n8.x4.shared.b16 {%0,%1,%2,%3}, [%4];"
                : "=r"(b0), "=r"(b1), "=r"(b2), "=r"(b3)
                : "r"(bb + (uint32_t)t * 16 * BPITCH + kk * 32));
            mma16816(acc[2 * t],     af[kk], b0, b1);
            mma16816(acc[2 * t + 1], af[kk], b2, b3);
        }
    }
}

// One pipeline iteration: LDG(next), scores(cc), syncwarp, MMA(cc-1)
__device__ __forceinline__ void iter(int sb, int cc, int w,
                                     ChunkBuf& cur, ChunkBuf& nxt,
                                     const float* gp0, const float* sp0,
                                     const float* s2p,
                                     uint32_t sts0, uint32_t lda0, uint32_t ldb,
                                     const float (&s1v)[4], const float (&bnv)[4],
                                     float (&dloc)[4], float (&acc)[8][4]) {
    // next score position (prefetch target)
    int nsb = sb, ncc = cc + 1;
    if (ncc == SBCH) { ncc = 0; nsb = sb + 1; }
    int cn = (nsb < SBN) ? nsb * SBCH + ((ncc + w) & 7) : 0;
    load_chunk(gp0, sp0, s2p, cn, nxt);

    do_scores(cur, cc & 1, sts0, s1v, bnv, dloc);
    __syncwarp();
    if (cc > 0)
        do_mma(sb * SBCH + ((cc - 1 + w) & 7), (cc - 1) & 1, lda0, ldb, acc);
}

__global__ __launch_bounds__(256, 2) void k_main(const float* __restrict__ geo,
                                                 const float* __restrict__ sem) {
    extern __shared__ __align__(16) char smem[];

    int tid = threadIdx.x, lane = tid & 31, w = tid >> 5;
    int rb = blockIdx.x >> 2, q = blockIdx.x & 3;
    int i0 = rb * 128, jbase = q * 2048;

    int subrow = lane >> 3, colseg = (lane & 7) * 4;

    const float* gp0 = geo + (size_t)(i0 + 16 * w + subrow) * NN + jbase + colseg;
    const float* sp0 = sem + (size_t)(i0 + 16 * w + subrow) * NN + jbase + colseg;
    const float* s2p = g_s2 + jbase + colseg;

    float Mv = g_M;
    float s1v[4], bnv[4];
#pragma unroll
    for (int i = 0; i < 4; i++) {
        s1v[i] = g_s1[i0 + 16 * w + 4 * i + subrow];
        bnv[i] = fmaxf(0.f, 2.f * (s1v[i] + Mv)) * LOG2E;
    }

    uint32_t smem0;
    asm("{ .reg .u64 t; cvta.to.shared.u64 t, %1; cvt.u32.u64 %0, t; }"
        : "=r"(smem0) : "l"(smem));
    uint32_t bbase = smem0;
    uint32_t sbuf  = smem0 + 2 * BBYTES + w * SWARP;

    uint32_t sts0 = sbuf + (uint32_t)subrow * SPITCH + (uint32_t)colseg * 2;
    uint32_t lda0 = sbuf + (uint32_t)(lane & 15) * SPITCH + (uint32_t)(lane >> 4) * 16;
    int ldrow = ((lane >> 4) & 1) * 8 + (lane & 7);
    int ldcol = ((lane >> 3) & 1) * 16;
    uint32_t ldb0 = bbase + (uint32_t)ldrow * BPITCH + ldcol;

    // B staging map
    int srow = tid >> 5, sseg = tid & 31;
    const __half* bsrc = g_hT + (size_t)srow * NN + jbase + sseg * 8;
    uint32_t bdst = bbase + (uint32_t)srow * BPITCH + sseg * 16;

    float acc[8][4];
#pragma unroll
    for (int i = 0; i < 8; i++)
#pragma unroll
        for (int j = 0; j < 4; j++) acc[i][j] = 0.f;
    float dloc[4] = {0.f, 0.f, 0.f, 0.f};

    // prologue: stage B superblock 0
#pragma unroll
    for (int p = 0; p < 8; p++)
        asm volatile("cp.async.cg.shared.global [%0], [%1], 16;"
                     :: "r"(bdst + (uint32_t)(8 * p) * BPITCH),
                        "l"(bsrc + (size_t)(8 * p) * NN));
    asm volatile("cp.async.commit_group;");
    asm volatile("cp.async.wait_group 0;");

    // prologue: warp w starts at its rotated chunk
    ChunkBuf A0, A1;
    load_chunk(gp0, sp0, s2p, w & 7, A0);
    __syncthreads();

    for (int sb = 0; sb < SBN; sb++) {
        // stage next superblock into buffer (sb+1)&1 — last mma on that buffer
        // drained before the previous superblock's closing __syncthreads
        if (sb + 1 < SBN) {
            int jblk = (sb + 1) * (SBCH * 32);
            uint32_t bd = bdst + (uint32_t)((sb + 1) & 1) * BBYTES;
#pragma unroll
            for (int p = 0; p < 8; p++)
                asm volatile("cp.async.cg.shared.global [%0], [%1], 16;"
                             :: "r"(bd + (uint32_t)(8 * p) * BPITCH),
                                "l"(bsrc + (size_t)(8 * p) * NN + jblk));
            asm volatile("cp.async.commit_group;");
        }

        uint32_t ldb = ldb0 + (uint32_t)(sb & 1) * BBYTES;
#pragma unroll
        for (int cc = 0; cc < SBCH; cc += 2) {
            iter(sb, cc,     w, A0, A1, gp0, sp0, s2p, sts0, lda0, ldb,
                 s1v, bnv, dloc, acc);
            iter(sb, cc + 1, w, A1, A0, gp0, sp0, s2p, sts0, lda0, ldb,
                 s1v, bnv, dloc, acc);
        }
        // drain: mma for the last score chunk of this superblock
        do_mma(sb * SBCH + ((7 + w) & 7), 1, lda0, ldb, acc);

        if (sb + 1 < SBN)
            asm volatile("cp.async.wait_group 0;");
        __syncthreads();
    }

    // ---- epilogue ----
#pragma unroll
    for (int i = 0; i < 4; i++) {
        float v = dloc[i];
        v += __shfl_xor_sync(0xffffffffu, v, 1);
        v += __shfl_xor_sync(0xffffffffu, v, 2);
        v += __shfl_xor_sync(0xffffffffu, v, 4);
        dloc[i] = v;
    }
    if ((lane & 7) == 0) {
#pragma unroll
        for (int i = 0; i < 4; i++)
            g_den[q * NN + i0 + 16 * w + 4 * i + subrow] = dloc[i];
    }

    // numerator partials: c-frag layout (r = lane>>2, tg = lane&3)
    int r = lane >> 2, tg = lane & 3;
    int row0 = i0 + 16 * w + r;
    float* dst0 = g_num + ((size_t)q * NN + row0) * OUT_F;
    float* dst1 = g_num + ((size_t)q * NN + row0 + 8) * OUT_F;
#pragma unroll
    for (int t = 0; t < 8; t++) {
        int n0 = 8 * t + 2 * tg;
        *(float2*)(dst0 + n0) = make_float2(acc[t][0], acc[t][1]);
        *(float2*)(dst1 + n0) = make_float2(acc[t][2], acc[t][3]);
    }
}

// ---------------------------------------------------------------------------
// Combine split-K partials: out = elu(sum(n)/sum(d))
// ---------------------------------------------------------------------------
__global__ __launch_bounds__(256) void k_fin(float* __restrict__ out) {
    int idx = blockIdx.x * 256 + threadIdx.x;     // 262144 threads
    int row = idx >> 5, qq = idx & 31;            // 32 threads/row, 2 floats
    float den = g_den[row] + g_den[NN + row] + g_den[2 * NN + row] + g_den[3 * NN + row];
    float inv = 1.0f / den;
    float2 n0 = *(const float2*)&g_num[(size_t)row * OUT_F + 2 * qq];
    float2 n1 = *(const float2*)&g_num[(size_t)(NN + row) * OUT_F + 2 * qq];
    float2 n2 = *(const float2*)&g_num[(size_t)(2 * NN + row) * OUT_F + 2 * qq];
    float2 n3 = *(const float2*)&g_num[(size_t)(3 * NN + row) * OUT_F + 2 * qq];
    float2 o;
    float v;
    v = (n0.x + n1.x + n2.x + n3.x) * inv; o.x = (v > 0.f) ? v : expm1f(v);
    v = (n0.y + n1.y + n2.y + n3.y) * inv; o.y = (v > 0.f) ? v : expm1f(v);
    *(float2*)&out[(size_t)row * OUT_F + 2 * qq] = o;
}

// ---------------------------------------------------------------------------
extern "C" void kernel_launch(void* const* d_in, const int* in_sizes, int n_in,
                              void* d_out, int out_size) {
    const float* geo  = (const float*)d_in[0];
    const float* sem  = (const float*)d_in[1];
    const float* feat = (const float*)d_in[2];
    const float* W    = (const float*)d_in[3];
    const float* a    = (const float*)d_in[4];
    float* out = (float*)d_out;

    cudaFuncSetAttribute(k_main, cudaFuncAttributeMaxDynamicSharedMemorySize, SMEMT);

    k_proj<<<NN / 16, 1024>>>(feat, W, a);
    k_max<<<1, 256>>>();
    k_main<<<256, 256, SMEMT>>>(geo, sem);
    k_fin<<<1024, 256>>>(out);
}

// round 14
// speedup vs baseline: 1.0672x; 1.0672x over previous
#include <cuda_runtime.h>
#include <cuda_fp16.h>
#include <cstdint>
#include <math.h>

#define NN 8192
#define IN_F 128
#define OUT_F 64
#define ALPHA 0.2f
#define LOG2E 1.4426950408889634f
#define NCH 64             // 32-col chunks over a 2048-col quarter
#define SBCH 8             // chunks per B superblock (256 cols)
#define SBN (NCH / SBCH)
#define BPITCH 528         // B smem row pitch -> 16B rotation, conflict-free
#define BBYTES (64 * BPITCH)
#define SPITCH 80          // score tile pitch -> 16B rotation, conflict-free
#define SWARP (2 * 16 * SPITCH)      // per-warp double-buffered score tile
#define SMEMT (2 * BBYTES + 8 * SWARP)   // 88064 B -> 2 CTAs/SM

// ---------------- device scratch (allocation-free rule) ----------------
__device__ float  g_s1[NN];
__device__ float  g_s2[NN];
__device__ float  g_M;
__device__ __half g_hT[(size_t)OUT_F * NN];     // H^T fp16, [f][j]
__device__ float  g_num[(size_t)4 * NN * OUT_F];
__device__ float  g_den[4 * NN];

// ---------------------------------------------------------------------------
// Kernel A: h = feat @ W^T ; s1/s2 row scores ; g_hT = fp16(h)^T
// ---------------------------------------------------------------------------
__global__ __launch_bounds__(1024) void k_proj(const float* __restrict__ feat,
                                               const float* __restrict__ W,
                                               const float* __restrict__ a) {
    __shared__ float Ws[OUT_F][IN_F + 4];
    __shared__ float Fs[16][IN_F];
    __shared__ float red1[32], red2[32];
    __shared__ __half Ts[OUT_F][18];

    int tid = threadIdx.x;
    int i0  = blockIdx.x * 16;

    for (int t = tid; t < OUT_F * IN_F; t += 1024)
        Ws[t / IN_F][t % IN_F] = W[t];
    for (int t = tid; t < 16 * IN_F; t += 1024)
        Fs[t / IN_F][t % IN_F] = feat[(size_t)(i0 + t / IN_F) * IN_F + (t % IN_F)];
    __syncthreads();

    int f = tid & 63;
    int r = tid >> 6;
    float acc = 0.f;
#pragma unroll
    for (int k = 0; k < IN_F; k += 4) {
        float4 fv = *(const float4*)&Fs[r][k];
        float4 wv = *(const float4*)&Ws[f][k];
        acc += fv.x * wv.x + fv.y * wv.y + fv.z * wv.z + fv.w * wv.w;
    }

    Ts[f][r] = __float2half(acc);

    float t1 = acc * a[f];
    float t2 = acc * a[OUT_F + f];
#pragma unroll
    for (int off = 16; off; off >>= 1) {
        t1 += __shfl_xor_sync(0xffffffffu, t1, off);
        t2 += __shfl_xor_sync(0xffffffffu, t2, off);
    }
    int w = tid >> 5;
    if ((tid & 31) == 0) { red1[w] = t1; red2[w] = t2; }
    __syncthreads();
    if (tid < 16) {
        g_s1[i0 + tid] = red1[2 * tid] + red1[2 * tid + 1];
        g_s2[i0 + tid] = red2[2 * tid] + red2[2 * tid + 1];
    }
    if (tid < 512) {
        int ff = tid >> 3, u = tid & 7;
        __half2 pk = __halves2half2(Ts[ff][2 * u], Ts[ff][2 * u + 1]);
        *(__half2*)&g_hT[(size_t)ff * NN + i0 + 2 * u] = pk;
    }
}

// ---------------------------------------------------------------------------
// Kernel B: g_M = max_j s2[j]
// ---------------------------------------------------------------------------
__global__ __launch_bounds__(256) void k_max() {
    __shared__ float red[8];
    int tid = threadIdx.x;
    float m = -1e30f;
    for (int i = tid; i < NN; i += 256) m = fmaxf(m, g_s2[i]);
#pragma unroll
    for (int off = 16; off; off >>= 1)
        m = fmaxf(m, __shfl_xor_sync(0xffffffffu, m, off));
    if ((tid & 31) == 0) red[tid >> 5] = m;
    __syncthreads();
    if (tid == 0) {
        float mm = red[0];
#pragma unroll
        for (int i = 1; i < 8; i++) mm = fmaxf(mm, red[i]);
        g_M = mm;
    }
}

// ---------------------------------------------------------------------------
// Main kernel. 256 CTAs (64 row-tiles x 4 quarters) x 256 threads, 2 CTAs/SM.
// R11 structure + depth-1 software pipeline on the B ldmatrix stream so the
// LDSM->HMMA dependency chains overlap instead of serializing.
// ---------------------------------------------------------------------------
struct ChunkBuf {
    float4 G[4];
    float4 S[4];
    float4 Z;
};

__device__ __forceinline__ void load_chunk(const float* __restrict__ gp0,
                                           const float* __restrict__ sp0,
                                           const float* __restrict__ s2p,
                                           int c, ChunkBuf& b) {
    size_t off = (size_t)c * 32;
#pragma unroll
    for (int i = 0; i < 4; i++) {
        b.G[i] = __ldcs((const float4*)(gp0 + off + (size_t)(4 * i) * NN));
        b.S[i] = __ldcs((const float4*)(sp0 + off + (size_t)(4 * i) * NN));
    }
    b.Z = *(const float4*)(s2p + off);
}

__device__ __forceinline__ void mma16816(float* d, const uint32_t* a,
                                         uint32_t b0, uint32_t b1) {
    asm volatile(
        "mma.sync.aligned.m16n8k16.row.col.f32.f16.f16.f32 "
        "{%0,%1,%2,%3},{%4,%5,%6,%7},{%8,%9},{%0,%1,%2,%3};"
        : "+f"(d[0]), "+f"(d[1]), "+f"(d[2]), "+f"(d[3])
        : "r"(a[0]), "r"(a[1]), "r"(a[2]), "r"(a[3]), "r"(b0), "r"(b1));
}

__device__ __forceinline__ void ldsm_x4(uint32_t* r, uint32_t addr) {
    asm volatile(
        "ldmatrix.sync.aligned.m8n8.x4.shared.b16 {%0,%1,%2,%3}, [%4];"
        : "=r"(r[0]), "=r"(r[1]), "=r"(r[2]), "=r"(r[3]) : "r"(addr));
}

__device__ __forceinline__ void proc_chunk(int c, int cn, int par,
                                           ChunkBuf& cur, ChunkBuf& nxt,
                                           const float* gp0, const float* sp0,
                                           const float* s2p,
                                           uint32_t sts0, uint32_t lda0, uint32_t ldb,
                                           const float (&s1v)[4], const float (&bnv)[4],
                                           float (&dloc)[4], float (&acc)[8][4]) {
    // 1. prefetch next chunk's adjacency (coalesced LDG.128)
    load_chunk(gp0, sp0, s2p, cn, nxt);

    uint32_t bufo = (uint32_t)par * (16 * SPITCH);

    // 2. scores in coalesced layout (4 rows x 4 cols per thread) -> smem
    __half2 dh[4];
#pragma unroll
    for (int i = 0; i < 4; i++) {
        float4 g = cur.G[i], s = cur.S[i];
        float clx = (g.x + s.x) * LOG2E;
        float cly = (g.y + s.y) * LOG2E;
        float clz = (g.z + s.z) * LOG2E;
        float clw = (g.w + s.w) * LOG2E;
        float s1 = s1v[i], bn = bnv[i];
        float x0 = s1 + cur.Z.x, x1 = s1 + cur.Z.y;
        float x2 = s1 + cur.Z.z, x3 = s1 + cur.Z.w;
        float l0 = fmaxf(x0, ALPHA * x0), l1 = fmaxf(x1, ALPHA * x1);
        float l2 = fmaxf(x2, ALPHA * x2), l3 = fmaxf(x3, ALPHA * x3);
        float p0 = (clx > 0.f) ? exp2f(fmaf(l0, clx, -bn)) : 0.f;
        float p1 = (cly > 0.f) ? exp2f(fmaf(l1, cly, -bn)) : 0.f;
        float p2 = (clz > 0.f) ? exp2f(fmaf(l2, clz, -bn)) : 0.f;
        float p3 = (clw > 0.f) ? exp2f(fmaf(l3, clw, -bn)) : 0.f;
        __half2 lo = __floats2half2_rn(p0, p1);
        __half2 hi = __floats2half2_rn(p2, p3);
        dh[i] = __hadd2(lo, hi);
        asm volatile("st.shared.v2.b32 [%0], {%1,%2};"
                     :: "r"(sts0 + bufo + (uint32_t)(4 * i) * SPITCH),
                        "r"(*(uint32_t*)&lo), "r"(*(uint32_t*)&hi));
    }

    __syncwarp();

    // 3. A-frags first (LDSM latency covered by the dloc arithmetic below)
    uint32_t af[2][4];
    uint32_t la = lda0 + bufo;
    ldsm_x4(af[0], la);
    ldsm_x4(af[1], la + 32);

#pragma unroll
    for (int i = 0; i < 4; i++) {
        float2 d = __half22float2(dh[i]);
        dloc[i] += d.x + d.y;
    }

    // 4. B-frag stream, depth-1 double buffered: ld(idx+1) issued before
    //    mma(idx) consumes -> LDSM latency overlaps the previous mma pair.
    uint32_t bb = ldb + (uint32_t)(c & (SBCH - 1)) * 64;
    uint32_t breg[2][4];
    ldsm_x4(breg[0], bb);
#pragma unroll
    for (int idx = 0; idx < 8; idx++) {
        if (idx < 7) {
            int nid = idx + 1;
            ldsm_x4(breg[nid & 1],
                    bb + (uint32_t)(nid & 3) * 16 * BPITCH + (uint32_t)(nid >> 2) * 32);
        }
        int kk = idx >> 2, t = idx & 3;
        mma16816(acc[2 * t],     af[kk], breg[idx & 1][0], breg[idx & 1][1]);
        mma16816(acc[2 * t + 1], af[kk], breg[idx & 1][2], breg[idx & 1][3]);
    }
}

__global__ __launch_bounds__(256, 2) void k_main(const float* __restrict__ geo,
                                                 const float* __restrict__ sem) {
    extern __shared__ __align__(16) char smem[];

    int tid = threadIdx.x, lane = tid & 31, w = tid >> 5;
    int rb = blockIdx.x >> 2, q = blockIdx.x & 3;
    int i0 = rb * 128, jbase = q * 2048;

    int subrow = lane >> 3, colseg = (lane & 7) * 4;

    const float* gp0 = geo + (size_t)(i0 + 16 * w + subrow) * NN + jbase + colseg;
    const float* sp0 = sem + (size_t)(i0 + 16 * w + subrow) * NN + jbase + colseg;
    const float* s2p = g_s2 + jbase + colseg;

    float Mv = g_M;
    float s1v[4], bnv[4];
#pragma unroll
    for (int i = 0; i < 4; i++) {
        s1v[i] = g_s1[i0 + 16 * w + 4 * i + subrow];
        bnv[i] = fmaxf(0.f, 2.f * (s1v[i] + Mv)) * LOG2E;
    }

    uint32_t smem0;
    asm("{ .reg .u64 t; cvta.to.shared.u64 t, %1; cvt.u32.u64 %0, t; }"
        : "=r"(smem0) : "l"(smem));
    uint32_t bbase = smem0;
    uint32_t sbuf  = smem0 + 2 * BBYTES + w * SWARP;

    uint32_t sts0 = sbuf + (uint32_t)subrow * SPITCH + (uint32_t)colseg * 2;
    uint32_t lda0 = sbuf + (uint32_t)(lane & 15) * SPITCH + (uint32_t)(lane >> 4) * 16;
    int ldrow = ((lane >> 4) & 1) * 8 + (lane & 7);
    int ldcol = ((lane >> 3) & 1) * 16;
    uint32_t ldb0 = bbase + (uint32_t)ldrow * BPITCH + ldcol;

    // B staging map
    int srow = tid >> 5, sseg = tid & 31;
    const __half* bsrc = g_hT + (size_t)srow * NN + jbase + sseg * 8;
    uint32_t bdst = bbase + (uint32_t)srow * BPITCH + sseg * 16;

    float acc[8][4];
#pragma unroll
    for (int i = 0; i < 8; i++)
#pragma unroll
        for (int j = 0; j < 4; j++) acc[i][j] = 0.f;
    float dloc[4] = {0.f, 0.f, 0.f, 0.f};

    // prologue: stage B superblock 0
#pragma unroll
    for (int p = 0; p < 8; p++)
        asm volatile("cp.async.cg.shared.global [%0], [%1], 16;"
                     :: "r"(bdst + (uint32_t)(8 * p) * BPITCH),
                        "l"(bsrc + (size_t)(8 * p) * NN));
    asm volatile("cp.async.commit_group;");
    asm volatile("cp.async.wait_group 0;");

    // prologue: warp w starts at its rotated chunk
    ChunkBuf A0, A1;
    load_chunk(gp0, sp0, s2p, w & 7, A0);
    __syncthreads();

    for (int sb = 0; sb < SBN; sb++) {
        if (sb + 1 < SBN) {
            int jblk = (sb + 1) * (SBCH * 32);
            uint32_t bd = bdst + (uint32_t)((sb + 1) & 1) * BBYTES;
#pragma unroll
            for (int p = 0; p < 8; p++)
                asm volatile("cp.async.cg.shared.global [%0], [%1], 16;"
                             :: "r"(bd + (uint32_t)(8 * p) * BPITCH),
                                "l"(bsrc + (size_t)(8 * p) * NN + jblk));
            asm volatile("cp.async.commit_group;");
        }

        uint32_t ldb = ldb0 + (uint32_t)(sb & 1) * BBYTES;
#pragma unroll
        for (int cc = 0; cc < SBCH; cc++) {
            int c = sb * SBCH + ((cc + w) & 7);
            int ncc = cc + 1, nsb = sb;
            if (ncc == SBCH) { ncc = 0; nsb = sb + 1; }
            int cn = (nsb < SBN) ? (nsb * SBCH + ((ncc + w) & 7)) : 0;
            if (cc & 1)
                proc_chunk(c, cn, 1, A1, A0, gp0, sp0, s2p, sts0, lda0, ldb,
                           s1v, bnv, dloc, acc);
            else
                proc_chunk(c, cn, 0, A0, A1, gp0, sp0, s2p, sts0, lda0, ldb,
                           s1v, bnv, dloc, acc);
        }

        asm volatile("cp.async.wait_group 0;");
        __syncthreads();
    }

    // ---- epilogue ----
#pragma unroll
    for (int i = 0; i < 4; i++) {
        float v = dloc[i];
        v += __shfl_xor_sync(0xffffffffu, v, 1);
        v += __shfl_xor_sync(0xffffffffu, v, 2);
        v += __shfl_xor_sync(0xffffffffu, v, 4);
        dloc[i] = v;
    }
    if ((lane & 7) == 0) {
#pragma unroll
        for (int i = 0; i < 4; i++)
            g_den[q * NN + i0 + 16 * w + 4 * i + subrow] = dloc[i];
    }

    // numerator partials: c-frag layout (r = lane>>2, tg = lane&3)
    int r = lane >> 2, tg = lane & 3;
    int row0 = i0 + 16 * w + r;
    float* dst0 = g_num + ((size_t)q * NN + row0) * OUT_F;
    float* dst1 = g_num + ((size_t)q * NN + row0 + 8) * OUT_F;
#pragma unroll
    for (int t = 0; t < 8; t++) {
        int n0 = 8 * t + 2 * tg;
        *(float2*)(dst0 + n0) = make_float2(acc[t][0], acc[t][1]);
        *(float2*)(dst1 + n0) = make_float2(acc[t][2], acc[t][3]);
    }
}

// ---------------------------------------------------------------------------
// Combine split-K partials: out = elu(sum(n)/sum(d))  (float4 / 512-block form)
// ---------------------------------------------------------------------------
__global__ __launch_bounds__(256) void k_fin(float* __restrict__ out) {
    int idx = blockIdx.x * 256 + threadIdx.x;
    int row = idx >> 4, qq = idx & 15;
    float den = g_den[row] + g_den[NN + row] + g_den[2 * NN + row] + g_den[3 * NN + row];
    float inv = 1.0f / den;
    float4 n0 = *(const float4*)&g_num[(size_t)row * OUT_F + 4 * qq];
    float4 n1 = *(const float4*)&g_num[(size_t)(NN + row) * OUT_F + 4 * qq];
    float4 n2 = *(const float4*)&g_num[(size_t)(2 * NN + row) * OUT_F + 4 * qq];
    float4 n3 = *(const float4*)&g_num[(size_t)(3 * NN + row) * OUT_F + 4 * qq];
    float4 o;
    float v;
    v = (n0.x + n1.x + n2.x + n3.x) * inv; o.x = (v > 0.f) ? v : expm1f(v);
    v = (n0.y + n1.y + n2.y + n3.y) * inv; o.y = (v > 0.f) ? v : expm1f(v);
    v = (n0.z + n1.z + n2.z + n3.z) * inv; o.z = (v > 0.f) ? v : expm1f(v);
    v = (n0.w + n1.w + n2.w + n3.w) * inv; o.w = (v > 0.f) ? v : expm1f(v);
    *(float4*)&out[(size_t)row * OUT_F + 4 * qq] = o;
}

// ---------------------------------------------------------------------------
extern "C" void kernel_launch(void* const* d_in, const int* in_sizes, int n_in,
                              void* d_out, int out_size) {
    const float* geo  = (const float*)d_in[0];
    const float* sem  = (const float*)d_in[1];
    const float* feat = (const float*)d_in[2];
    const float* W    = (const float*)d_in[3];
    const float* a    = (const float*)d_in[4];
    float* out = (float*)d_out;

    cudaFuncSetAttribute(k_main, cudaFuncAttributeMaxDynamicSharedMemorySize, SMEMT);

    k_proj<<<NN / 16, 1024>>>(feat, W, a);
    k_max<<<1, 256>>>();
    k_main<<<256, 256, SMEMT>>>(geo, sem);
    k_fin<<<512, 256>>>(out);
}